// round 14
// baseline (speedup 1.0000x reference)
#include <cuda_runtime.h>

// Problem dims
#define NB   16      // batch
#define NQ   128     // queries
#define NK   512     // keys
#define NH   256     // hidden
#define NV   256     // value dim

// Scratch for projected q/k (no cudaMalloc allowed)
__device__ float g_qp[NB * NQ * NH];   // 2 MB
__device__ float g_kp[NB * NK * NH];   // 8 MB

// ---------------------------------------------------------------------------
// helpers
// ---------------------------------------------------------------------------
__device__ __forceinline__ float tanh_fast(float x) {
    float y;
    asm("tanh.approx.f32 %0, %1;" : "=f"(y) : "f"(x));
    return y;
}
__device__ __forceinline__ unsigned long long pk2(float lo, float hi) {
    unsigned long long r;
    asm("mov.b64 %0, {%1, %2};" : "=l"(r) : "f"(lo), "f"(hi));
    return r;
}
__device__ __forceinline__ void upk2(unsigned long long v, float &lo, float &hi) {
    asm("mov.b64 {%0, %1}, %2;" : "=f"(lo), "=f"(hi) : "l"(v));
}
__device__ __forceinline__ unsigned long long ffma2(unsigned long long a,
                                                    unsigned long long b,
                                                    unsigned long long c) {
    unsigned long long d;
    asm("fma.rn.f32x2 %0, %1, %2, %3;" : "=l"(d) : "l"(a), "l"(b), "l"(c));
    return d;
}

// ---------------------------------------------------------------------------
// Projection GEMM:  C[m, n] = sum_d A[m, d] * W[n, d]   (both K-major, NT)
// One launch does BOTH projections: block.x tiles 0..15 -> queries/Wq -> g_qp,
// tiles 16..79 -> keys/Wk -> g_kp.  BM=128, BN=64, BK=32, 128 threads,
// 8x8 microtile, f32x2 packed FFMA2 accumulators.
// Key tiles whose rows are all >= valid_len[batch] produce never-read output
// and exit immediately.
// ---------------------------------------------------------------------------
#define QTILES 16   // 2048 / 128
#define KTILES 64   // 8192 / 128

__global__ __launch_bounds__(128)
void proj_gemm_kernel(const float *__restrict__ Aq, const float *__restrict__ Wq,
                      const float *__restrict__ Ak, const float *__restrict__ Wk,
                      const int *__restrict__ vlens,
                      float *__restrict__ Cq, float *__restrict__ Ck)
{
    __shared__ float As[32][128];   // [k][m] (transposed)
    __shared__ float Bs[32][64];    // [k][n] (transposed)

    const int tid = threadIdx.x;
    const int bx  = blockIdx.x;

    const float *A, *W;
    float *C;
    int mb;
    if (bx < QTILES) { A = Aq; W = Wq; C = Cq; mb = bx * 128; }
    else {
        A = Ak; W = Wk; C = Ck; mb = (bx - QTILES) * 128;
        // Dead-tile skip: local key row within batch >= vlen -> output unused
        const int batch = mb >> 9;          // / NK
        const int local = mb & (NK - 1);
        if (local >= vlens[batch]) return;
    }
    const int nb = blockIdx.y * 64;

    const int tx = tid & 7;    // 0..7  -> cols tx*8
    const int ty = tid >> 3;   // 0..15 -> rows ty*8

    unsigned long long acc[8][4];
#pragma unroll
    for (int i = 0; i < 8; i++)
#pragma unroll
        for (int j = 0; j < 4; j++) acc[i][j] = 0ULL;

    for (int kb = 0; kb < NH; kb += 32) {
        // load A tile: thread loads row (mb+tid), 32 k-floats (8 float4)
#pragma unroll
        for (int i = 0; i < 8; i++) {
            float4 v = *(const float4 *)(A + (mb + tid) * NH + kb + i * 4);
            As[i * 4 + 0][tid] = v.x;
            As[i * 4 + 1][tid] = v.y;
            As[i * 4 + 2][tid] = v.z;
            As[i * 4 + 3][tid] = v.w;
        }
        // load W tile: 64 rows x 32 k = 512 float4, 4 per thread
#pragma unroll
        for (int i = 0; i < 4; i++) {
            int idx = tid + 128 * i;
            int n = idx & 63, kq = idx >> 6;
            float4 v = *(const float4 *)(W + (nb + n) * NH + kb + kq * 4);
            Bs[kq * 4 + 0][n] = v.x;
            Bs[kq * 4 + 1][n] = v.y;
            Bs[kq * 4 + 2][n] = v.z;
            Bs[kq * 4 + 3][n] = v.w;
        }
        __syncthreads();

#pragma unroll 8
        for (int kk = 0; kk < 32; kk++) {
            float4 aa0 = *(const float4 *)&As[kk][ty * 8];
            float4 aa1 = *(const float4 *)&As[kk][ty * 8 + 4];
            ulonglong2 b0 = *(const ulonglong2 *)&Bs[kk][tx * 8];
            ulonglong2 b1 = *(const ulonglong2 *)&Bs[kk][tx * 8 + 4];
            float av[8] = {aa0.x, aa0.y, aa0.z, aa0.w, aa1.x, aa1.y, aa1.z, aa1.w};
#pragma unroll
            for (int i = 0; i < 8; i++) {
                unsigned long long a2 = pk2(av[i], av[i]);
                acc[i][0] = ffma2(a2, b0.x, acc[i][0]);
                acc[i][1] = ffma2(a2, b0.y, acc[i][1]);
                acc[i][2] = ffma2(a2, b1.x, acc[i][2]);
                acc[i][3] = ffma2(a2, b1.y, acc[i][3]);
            }
        }
        __syncthreads();
    }

#pragma unroll
    for (int i = 0; i < 8; i++) {
        float o[8];
#pragma unroll
        for (int j = 0; j < 4; j++) upk2(acc[i][j], o[2 * j], o[2 * j + 1]);
        float *cp = C + (mb + ty * 8 + i) * NH + nb + tx * 8;
        *(float4 *)cp = make_float4(o[0], o[1], o[2], o[3]);
        *(float4 *)(cp + 4) = make_float4(o[4], o[5], o[6], o[7]);
    }
}

// ---------------------------------------------------------------------------
// Attention kernel: per q-row, scores -> masked softmax -> attn @ V.
// 256 threads (8 warps), 4 CTAs/SM. Phase 1: each warp owns keys {w, w+8,...}
// and BREAKS once the key index passes valid_len (masked keys need no work).
// Phase 3 trims its k-loop to valid_len (weights beyond are exact zeros).
// Grid = 592 (exactly 4 CTAs / SM).
// ---------------------------------------------------------------------------
#define ATT_GRID 592

__global__ __launch_bounds__(256, 4)
void attn_kernel(const float *__restrict__ values, const float *__restrict__ Wv,
                 const int *__restrict__ vlens, float *__restrict__ out)
{
    __shared__ float  s_sc[NK];
    __shared__ float  s_red[8];
    __shared__ float4 s_acc[3][64];

    const int tid  = threadIdx.x;
    const int lane = tid & 31;
    const int warp = tid >> 5;

    const float4 wv0 = *(const float4 *)(Wv + lane * 8);
    const float4 wv1 = *(const float4 *)(Wv + lane * 8 + 4);

    for (int row = blockIdx.x; row < NB * NQ; row += ATT_GRID) {
        const int b = row >> 7;
        const int vlen = vlens[b];
        const float *qr = g_qp + row * NH + lane * 8;
        const float4 q0 = *(const float4 *)qr;
        const float4 q1 = *(const float4 *)(qr + 4);
        const float *kbase = g_kp + b * NK * NH + lane * 8;

        // ---- Phase 1: scores (only keys < vlen; rest masked in phase 2) ----
        for (int kk = 0; kk < 32; kk++) {
            const int k0 = warp + kk * 16;
            if (k0 >= vlen) break;       // uniform per-warp; later kk larger
            const int k1 = k0 + 8;
            const float *kr0 = kbase + k0 * NH;
            const float *kr1 = kbase + k1 * NH;
            float4 a0 = *(const float4 *)kr0;
            float4 a1 = *(const float4 *)(kr0 + 4);
            float4 c0 = *(const float4 *)kr1;
            float4 c1 = *(const float4 *)(kr1 + 4);

            float p0 = wv0.x * tanh_fast(q0.x + a0.x);
            float p1 = wv0.x * tanh_fast(q0.x + c0.x);
            p0 = fmaf(wv0.y, tanh_fast(q0.y + a0.y), p0);
            p1 = fmaf(wv0.y, tanh_fast(q0.y + c0.y), p1);
            p0 = fmaf(wv0.z, tanh_fast(q0.z + a0.z), p0);
            p1 = fmaf(wv0.z, tanh_fast(q0.z + c0.z), p1);
            p0 = fmaf(wv0.w, tanh_fast(q0.w + a0.w), p0);
            p1 = fmaf(wv0.w, tanh_fast(q0.w + c0.w), p1);
            p0 = fmaf(wv1.x, tanh_fast(q1.x + a1.x), p0);
            p1 = fmaf(wv1.x, tanh_fast(q1.x + c1.x), p1);
            p0 = fmaf(wv1.y, tanh_fast(q1.y + a1.y), p0);
            p1 = fmaf(wv1.y, tanh_fast(q1.y + c1.y), p1);
            p0 = fmaf(wv1.z, tanh_fast(q1.z + a1.z), p0);
            p1 = fmaf(wv1.z, tanh_fast(q1.z + c1.z), p1);
            p0 = fmaf(wv1.w, tanh_fast(q1.w + a1.w), p0);
            p1 = fmaf(wv1.w, tanh_fast(q1.w + c1.w), p1);

#pragma unroll
            for (int o = 16; o > 0; o >>= 1) {
                p0 += __shfl_xor_sync(0xffffffffu, p0, o);
                p1 += __shfl_xor_sync(0xffffffffu, p1, o);
            }
            if (lane == 0) { s_sc[k0] = p0; s_sc[k1] = p1; }
        }
        __syncthreads();

        // ---- Phase 2: masked softmax (normalization deferred to phase 3) ----
        const float s0 = (tid < vlen) ? s_sc[tid] : -1e6f;
        const float s1 = (tid + 256 < vlen) ? s_sc[tid + 256] : -1e6f;

        float m = fmaxf(s0, s1);
#pragma unroll
        for (int o = 16; o > 0; o >>= 1) m = fmaxf(m, __shfl_xor_sync(0xffffffffu, m, o));
        if (lane == 0) s_red[warp] = m;
        __syncthreads();
        float bm = s_red[0];
#pragma unroll
        for (int j = 1; j < 8; j++) bm = fmaxf(bm, s_red[j]);

        const float e0 = __expf(s0 - bm);
        const float e1 = __expf(s1 - bm);
        __syncthreads();                 // everyone consumed s_red (max)
        s_sc[tid] = e0;
        s_sc[tid + 256] = e1;
        float ps = e0 + e1;
#pragma unroll
        for (int o = 16; o > 0; o >>= 1) ps += __shfl_xor_sync(0xffffffffu, ps, o);
        if (lane == 0) s_red[warp] = ps;
        __syncthreads();
        const float tot = s_red[0] + s_red[1] + s_red[2] + s_red[3] +
                          s_red[4] + s_red[5] + s_red[6] + s_red[7];
        const float inv = 1.0f / tot;

        // ---- Phase 3: out = attn @ V (weights >= vlen are exact zeros) ----
        const int vq  = tid & 63;        // column group (4 floats)
        const int kof = tid >> 6;        // key offset group 0..3
        const float *vb = values + b * NK * NV + vq * 4;
        float4 acc = make_float4(0.f, 0.f, 0.f, 0.f);
#pragma unroll 4
        for (int k = kof; k < vlen; k += 4) {
            const float a = s_sc[k];
            const float4 v = *(const float4 *)(vb + k * NV);
            acc.x = fmaf(a, v.x, acc.x);
            acc.y = fmaf(a, v.y, acc.y);
            acc.z = fmaf(a, v.z, acc.z);
            acc.w = fmaf(a, v.w, acc.w);
        }
        if (kof > 0) s_acc[kof - 1][vq] = acc;
        __syncthreads();
        if (kof == 0) {
            const float4 x1 = s_acc[0][vq];
            const float4 x2 = s_acc[1][vq];
            const float4 x3 = s_acc[2][vq];
            acc.x = (acc.x + x1.x + x2.x + x3.x) * inv;
            acc.y = (acc.y + x1.y + x2.y + x3.y) * inv;
            acc.z = (acc.z + x1.z + x2.z + x3.z) * inv;
            acc.w = (acc.w + x1.w + x2.w + x3.w) * inv;
            *(float4 *)(out + row * NV + vq * 4) = acc;
        }
        __syncthreads();
    }
}

// ---------------------------------------------------------------------------
extern "C" void kernel_launch(void *const *d_in, const int *in_sizes, int n_in,
                              void *d_out, int out_size)
{
    const float *queries = (const float *)d_in[0];
    const float *keys    = (const float *)d_in[1];
    const float *values  = (const float *)d_in[2];
    const float *Wq      = (const float *)d_in[3];
    const float *Wk      = (const float *)d_in[4];
    const float *Wv      = (const float *)d_in[5];
    const int   *vlens   = (const int *)d_in[6];
    float *out = (float *)d_out;

    float *qp_ptr = nullptr, *kp_ptr = nullptr;
    cudaGetSymbolAddress((void **)&qp_ptr, g_qp);
    cudaGetSymbolAddress((void **)&kp_ptr, g_kp);

    proj_gemm_kernel<<<dim3(QTILES + KTILES, NH / 64), 128>>>(
        queries, Wq, keys, Wk, vlens, qp_ptr, kp_ptr);
    attn_kernel<<<ATT_GRID, 256>>>(values, Wv, vlens, out);
}

// round 15
// speedup vs baseline: 1.0093x; 1.0093x over previous
#include <cuda_runtime.h>

// Problem dims
#define NB   16      // batch
#define NQ   128     // queries
#define NK   512     // keys
#define NH   256     // hidden
#define NV   256     // value dim

// Scratch for projected q/k (no cudaMalloc allowed)
__device__ float g_qp[NB * NQ * NH];   // 2 MB
__device__ float g_kp[NB * NK * NH];   // 8 MB

// ---------------------------------------------------------------------------
// helpers
// ---------------------------------------------------------------------------
__device__ __forceinline__ float tanh_fast(float x) {
    float y;
    asm("tanh.approx.f32 %0, %1;" : "=f"(y) : "f"(x));
    return y;
}
__device__ __forceinline__ unsigned long long pk2(float lo, float hi) {
    unsigned long long r;
    asm("mov.b64 %0, {%1, %2};" : "=l"(r) : "f"(lo), "f"(hi));
    return r;
}
__device__ __forceinline__ void upk2(unsigned long long v, float &lo, float &hi) {
    asm("mov.b64 {%0, %1}, %2;" : "=f"(lo), "=f"(hi) : "l"(v));
}
__device__ __forceinline__ unsigned long long ffma2(unsigned long long a,
                                                    unsigned long long b,
                                                    unsigned long long c) {
    unsigned long long d;
    asm("fma.rn.f32x2 %0, %1, %2, %3;" : "=l"(d) : "l"(a), "l"(b), "l"(c));
    return d;
}

// ---------------------------------------------------------------------------
// Projection GEMM:  C[m, n] = sum_d A[m, d] * W[n, d]   (both K-major, NT)
// One launch does BOTH projections: block.x tiles 0..15 -> queries/Wq -> g_qp,
// tiles 16..79 -> keys/Wk -> g_kp.  BM=128, BN=64, BK=32, 128 threads,
// 8x8 microtile, f32x2 packed FFMA2 accumulators.
// Key tiles whose rows are all >= valid_len[batch] produce never-read output
// and exit immediately.
// ---------------------------------------------------------------------------
#define QTILES 16   // 2048 / 128
#define KTILES 64   // 8192 / 128

__global__ __launch_bounds__(128)
void proj_gemm_kernel(const float *__restrict__ Aq, const float *__restrict__ Wq,
                      const float *__restrict__ Ak, const float *__restrict__ Wk,
                      const int *__restrict__ vlens,
                      float *__restrict__ Cq, float *__restrict__ Ck)
{
    __shared__ float As[32][128];   // [k][m] (transposed)
    __shared__ float Bs[32][64];    // [k][n] (transposed)

    const int tid = threadIdx.x;
    const int bx  = blockIdx.x;

    const float *A, *W;
    float *C;
    int mb;
    if (bx < QTILES) { A = Aq; W = Wq; C = Cq; mb = bx * 128; }
    else {
        A = Ak; W = Wk; C = Ck; mb = (bx - QTILES) * 128;
        // Dead-tile skip: local key row within batch >= vlen -> output unused
        const int batch = mb >> 9;          // / NK
        const int local = mb & (NK - 1);
        if (local >= vlens[batch]) return;
    }
    const int nb = blockIdx.y * 64;

    const int tx = tid & 7;    // 0..7  -> cols tx*8
    const int ty = tid >> 3;   // 0..15 -> rows ty*8

    unsigned long long acc[8][4];
#pragma unroll
    for (int i = 0; i < 8; i++)
#pragma unroll
        for (int j = 0; j < 4; j++) acc[i][j] = 0ULL;

    for (int kb = 0; kb < NH; kb += 32) {
        // load A tile: thread loads row (mb+tid), 32 k-floats (8 float4)
#pragma unroll
        for (int i = 0; i < 8; i++) {
            float4 v = *(const float4 *)(A + (mb + tid) * NH + kb + i * 4);
            As[i * 4 + 0][tid] = v.x;
            As[i * 4 + 1][tid] = v.y;
            As[i * 4 + 2][tid] = v.z;
            As[i * 4 + 3][tid] = v.w;
        }
        // load W tile: 64 rows x 32 k = 512 float4, 4 per thread
#pragma unroll
        for (int i = 0; i < 4; i++) {
            int idx = tid + 128 * i;
            int n = idx & 63, kq = idx >> 6;
            float4 v = *(const float4 *)(W + (nb + n) * NH + kb + kq * 4);
            Bs[kq * 4 + 0][n] = v.x;
            Bs[kq * 4 + 1][n] = v.y;
            Bs[kq * 4 + 2][n] = v.z;
            Bs[kq * 4 + 3][n] = v.w;
        }
        __syncthreads();

#pragma unroll 8
        for (int kk = 0; kk < 32; kk++) {
            float4 aa0 = *(const float4 *)&As[kk][ty * 8];
            float4 aa1 = *(const float4 *)&As[kk][ty * 8 + 4];
            ulonglong2 b0 = *(const ulonglong2 *)&Bs[kk][tx * 8];
            ulonglong2 b1 = *(const ulonglong2 *)&Bs[kk][tx * 8 + 4];
            float av[8] = {aa0.x, aa0.y, aa0.z, aa0.w, aa1.x, aa1.y, aa1.z, aa1.w};
#pragma unroll
            for (int i = 0; i < 8; i++) {
                unsigned long long a2 = pk2(av[i], av[i]);
                acc[i][0] = ffma2(a2, b0.x, acc[i][0]);
                acc[i][1] = ffma2(a2, b0.y, acc[i][1]);
                acc[i][2] = ffma2(a2, b1.x, acc[i][2]);
                acc[i][3] = ffma2(a2, b1.y, acc[i][3]);
            }
        }
        __syncthreads();
    }

#pragma unroll
    for (int i = 0; i < 8; i++) {
        float o[8];
#pragma unroll
        for (int j = 0; j < 4; j++) upk2(acc[i][j], o[2 * j], o[2 * j + 1]);
        float *cp = C + (mb + ty * 8 + i) * NH + nb + tx * 8;
        *(float4 *)cp = make_float4(o[0], o[1], o[2], o[3]);
        *(float4 *)(cp + 4) = make_float4(o[4], o[5], o[6], o[7]);
    }
}

// ---------------------------------------------------------------------------
// Attention kernel: per q-row, scores -> masked softmax -> attn @ V.
// 256 threads (8 warps), 4 CTAs/SM. Phase 1: each warp owns keys {w, w+8,...}
// and BREAKS once the key index passes valid_len (masked keys need no work).
// Phase 3 trims its k-loop to valid_len (weights beyond are exact zeros).
// Grid = 592 (exactly 4 CTAs / SM).
// ---------------------------------------------------------------------------
#define ATT_GRID 592

__global__ __launch_bounds__(256, 4)
void attn_kernel(const float *__restrict__ values, const float *__restrict__ Wv,
                 const int *__restrict__ vlens, float *__restrict__ out)
{
    __shared__ float  s_sc[NK];
    __shared__ float  s_red[8];
    __shared__ float4 s_acc[3][64];

    const int tid  = threadIdx.x;
    const int lane = tid & 31;
    const int warp = tid >> 5;

    const float4 wv0 = *(const float4 *)(Wv + lane * 8);
    const float4 wv1 = *(const float4 *)(Wv + lane * 8 + 4);

    for (int row = blockIdx.x; row < NB * NQ; row += ATT_GRID) {
        const int b = row >> 7;
        const int vlen = vlens[b];
        const float *qr = g_qp + row * NH + lane * 8;
        const float4 q0 = *(const float4 *)qr;
        const float4 q1 = *(const float4 *)(qr + 4);
        const float *kbase = g_kp + b * NK * NH + lane * 8;

        // ---- Phase 1: scores (only keys < vlen; rest masked in phase 2) ----
        for (int kk = 0; kk < 32; kk++) {
            const int k0 = warp + kk * 16;
            if (k0 >= vlen) break;       // uniform per-warp; later kk larger
            const int k1 = k0 + 8;
            const float *kr0 = kbase + k0 * NH;
            const float *kr1 = kbase + k1 * NH;
            float4 a0 = *(const float4 *)kr0;
            float4 a1 = *(const float4 *)(kr0 + 4);
            float4 c0 = *(const float4 *)kr1;
            float4 c1 = *(const float4 *)(kr1 + 4);

            float p0 = wv0.x * tanh_fast(q0.x + a0.x);
            float p1 = wv0.x * tanh_fast(q0.x + c0.x);
            p0 = fmaf(wv0.y, tanh_fast(q0.y + a0.y), p0);
            p1 = fmaf(wv0.y, tanh_fast(q0.y + c0.y), p1);
            p0 = fmaf(wv0.z, tanh_fast(q0.z + a0.z), p0);
            p1 = fmaf(wv0.z, tanh_fast(q0.z + c0.z), p1);
            p0 = fmaf(wv0.w, tanh_fast(q0.w + a0.w), p0);
            p1 = fmaf(wv0.w, tanh_fast(q0.w + c0.w), p1);
            p0 = fmaf(wv1.x, tanh_fast(q1.x + a1.x), p0);
            p1 = fmaf(wv1.x, tanh_fast(q1.x + c1.x), p1);
            p0 = fmaf(wv1.y, tanh_fast(q1.y + a1.y), p0);
            p1 = fmaf(wv1.y, tanh_fast(q1.y + c1.y), p1);
            p0 = fmaf(wv1.z, tanh_fast(q1.z + a1.z), p0);
            p1 = fmaf(wv1.z, tanh_fast(q1.z + c1.z), p1);
            p0 = fmaf(wv1.w, tanh_fast(q1.w + a1.w), p0);
            p1 = fmaf(wv1.w, tanh_fast(q1.w + c1.w), p1);

#pragma unroll
            for (int o = 16; o > 0; o >>= 1) {
                p0 += __shfl_xor_sync(0xffffffffu, p0, o);
                p1 += __shfl_xor_sync(0xffffffffu, p1, o);
            }
            if (lane == 0) { s_sc[k0] = p0; s_sc[k1] = p1; }
        }
        __syncthreads();

        // ---- Phase 2: masked softmax (normalization deferred to phase 3) ----
        const float s0 = (tid < vlen) ? s_sc[tid] : -1e6f;
        const float s1 = (tid + 256 < vlen) ? s_sc[tid + 256] : -1e6f;

        float m = fmaxf(s0, s1);
#pragma unroll
        for (int o = 16; o > 0; o >>= 1) m = fmaxf(m, __shfl_xor_sync(0xffffffffu, m, o));
        if (lane == 0) s_red[warp] = m;
        __syncthreads();
        float bm = s_red[0];
#pragma unroll
        for (int j = 1; j < 8; j++) bm = fmaxf(bm, s_red[j]);

        const float e0 = __expf(s0 - bm);
        const float e1 = __expf(s1 - bm);
        __syncthreads();                 // everyone consumed s_red (max)
        s_sc[tid] = e0;
        s_sc[tid + 256] = e1;
        float ps = e0 + e1;
#pragma unroll
        for (int o = 16; o > 0; o >>= 1) ps += __shfl_xor_sync(0xffffffffu, ps, o);
        if (lane == 0) s_red[warp] = ps;
        __syncthreads();
        const float tot = s_red[0] + s_red[1] + s_red[2] + s_red[3] +
                          s_red[4] + s_red[5] + s_red[6] + s_red[7];
        const float inv = 1.0f / tot;

        // ---- Phase 3: out = attn @ V (weights >= vlen are exact zeros) ----
        const int vq  = tid & 63;        // column group (4 floats)
        const int kof = tid >> 6;        // key offset group 0..3
        const float *vb = values + b * NK * NV + vq * 4;
        float4 acc = make_float4(0.f, 0.f, 0.f, 0.f);
#pragma unroll 4
        for (int k = kof; k < vlen; k += 4) {
            const float a = s_sc[k];
            const float4 v = *(const float4 *)(vb + k * NV);
            acc.x = fmaf(a, v.x, acc.x);
            acc.y = fmaf(a, v.y, acc.y);
            acc.z = fmaf(a, v.z, acc.z);
            acc.w = fmaf(a, v.w, acc.w);
        }
        if (kof > 0) s_acc[kof - 1][vq] = acc;
        __syncthreads();
        if (kof == 0) {
            const float4 x1 = s_acc[0][vq];
            const float4 x2 = s_acc[1][vq];
            const float4 x3 = s_acc[2][vq];
            acc.x = (acc.x + x1.x + x2.x + x3.x) * inv;
            acc.y = (acc.y + x1.y + x2.y + x3.y) * inv;
            acc.z = (acc.z + x1.z + x2.z + x3.z) * inv;
            acc.w = (acc.w + x1.w + x2.w + x3.w) * inv;
            *(float4 *)(out + row * NV + vq * 4) = acc;
        }
        __syncthreads();
    }
}

// ---------------------------------------------------------------------------
extern "C" void kernel_launch(void *const *d_in, const int *in_sizes, int n_in,
                              void *d_out, int out_size)
{
    const float *queries = (const float *)d_in[0];
    const float *keys    = (const float *)d_in[1];
    const float *values  = (const float *)d_in[2];
    const float *Wq      = (const float *)d_in[3];
    const float *Wk      = (const float *)d_in[4];
    const float *Wv      = (const float *)d_in[5];
    const int   *vlens   = (const int *)d_in[6];
    float *out = (float *)d_out;

    float *qp_ptr = nullptr, *kp_ptr = nullptr;
    cudaGetSymbolAddress((void **)&qp_ptr, g_qp);
    cudaGetSymbolAddress((void **)&kp_ptr, g_kp);

    proj_gemm_kernel<<<dim3(QTILES + KTILES, NH / 64), 128>>>(
        queries, Wq, keys, Wk, vlens, qp_ptr, kp_ptr);
    attn_kernel<<<ATT_GRID, 256>>>(values, Wv, vlens, out);
}

// round 16
// speedup vs baseline: 1.1638x; 1.1532x over previous
#include <cuda_runtime.h>

// Problem dims
#define NB   16      // batch
#define NQ   128     // queries
#define NK   512     // keys
#define NH   256     // hidden
#define NV   256     // value dim

// Scratch for projected q/k (no cudaMalloc allowed)
__device__ float g_qp[NB * NQ * NH];   // 2 MB
__device__ float g_kp[NB * NK * NH];   // 8 MB

// ---------------------------------------------------------------------------
// helpers
// ---------------------------------------------------------------------------
__device__ __forceinline__ float tanh_fast(float x) {
    float y;
    asm("tanh.approx.f32 %0, %1;" : "=f"(y) : "f"(x));
    return y;
}
__device__ __forceinline__ unsigned long long pk2(float lo, float hi) {
    unsigned long long r;
    asm("mov.b64 %0, {%1, %2};" : "=l"(r) : "f"(lo), "f"(hi));
    return r;
}
__device__ __forceinline__ void upk2(unsigned long long v, float &lo, float &hi) {
    asm("mov.b64 {%0, %1}, %2;" : "=f"(lo), "=f"(hi) : "l"(v));
}
__device__ __forceinline__ unsigned long long ffma2(unsigned long long a,
                                                    unsigned long long b,
                                                    unsigned long long c) {
    unsigned long long d;
    asm("fma.rn.f32x2 %0, %1, %2, %3;" : "=l"(d) : "l"(a), "l"(b), "l"(c));
    return d;
}

// ---------------------------------------------------------------------------
// Projection GEMM:  C[m, n] = sum_d A[m, d] * W[n, d]   (both K-major, NT)
// BM=64, BN=64, BK=32, 128 threads, 8x4 microtile, f32x2 FFMA2 accumulators.
// block.x tiles 0..31 -> queries/Wq -> g_qp; 32..159 -> keys/Wk -> g_kp.
// Key tiles entirely beyond valid_len[batch] exit immediately (finer 64-row
// granularity than before).
// ---------------------------------------------------------------------------
#define QTILES 32    // 2048 / 64
#define KTILES 128   // 8192 / 64

__global__ __launch_bounds__(128)
void proj_gemm_kernel(const float *__restrict__ Aq, const float *__restrict__ Wq,
                      const float *__restrict__ Ak, const float *__restrict__ Wk,
                      const int *__restrict__ vlens,
                      float *__restrict__ Cq, float *__restrict__ Ck)
{
    __shared__ float As[32][68];    // [k][m], padded: conflict-free LDS
    __shared__ float Bs[32][64];    // [k][n]

    const int tid = threadIdx.x;
    const int bx  = blockIdx.x;

    const float *A, *W;
    float *C;
    int mb;
    if (bx < QTILES) { A = Aq; W = Wq; C = Cq; mb = bx * 64; }
    else {
        A = Ak; W = Wk; C = Ck; mb = (bx - QTILES) * 64;
        const int batch = mb >> 9;          // / NK
        const int local = mb & (NK - 1);
        if (local >= vlens[batch]) return;  // output never read
    }
    const int nb = blockIdx.y * 64;

    const int tx = tid & 15;   // 0..15 -> cols tx*4
    const int ty = tid >> 4;   // 0..7  -> rows ty*8

    const int arow  = tid >> 1;        // 0..63
    const int ahalf = tid & 1;         // 0..1 (16 k-floats each)

    unsigned long long acc[8][2];
#pragma unroll
    for (int i = 0; i < 8; i++) { acc[i][0] = 0ULL; acc[i][1] = 0ULL; }

    for (int kb = 0; kb < NH; kb += 32) {
        // A tile: 64 rows x 32 k. Thread: row=tid>>1, 16 k-floats (4 float4)
#pragma unroll
        for (int j = 0; j < 4; j++) {
            const int k0 = ahalf * 16 + j * 4;
            float4 v = *(const float4 *)(A + (mb + arow) * NH + kb + k0);
            As[k0 + 0][arow] = v.x;
            As[k0 + 1][arow] = v.y;
            As[k0 + 2][arow] = v.z;
            As[k0 + 3][arow] = v.w;
        }
        // W tile: 64 n-rows x 32 k = 512 float4, 4 per thread
#pragma unroll
        for (int j = 0; j < 4; j++) {
            const int idx = tid + 128 * j;
            const int n = idx & 63, kq = idx >> 6;
            float4 v = *(const float4 *)(W + (nb + n) * NH + kb + kq * 4);
            Bs[kq * 4 + 0][n] = v.x;
            Bs[kq * 4 + 1][n] = v.y;
            Bs[kq * 4 + 2][n] = v.z;
            Bs[kq * 4 + 3][n] = v.w;
        }
        __syncthreads();

#pragma unroll 8
        for (int kk = 0; kk < 32; kk++) {
            float4 aa0 = *(const float4 *)&As[kk][ty * 8];
            float4 aa1 = *(const float4 *)&As[kk][ty * 8 + 4];
            ulonglong2 b = *(const ulonglong2 *)&Bs[kk][tx * 4];
            float av[8] = {aa0.x, aa0.y, aa0.z, aa0.w, aa1.x, aa1.y, aa1.z, aa1.w};
#pragma unroll
            for (int i = 0; i < 8; i++) {
                unsigned long long a2 = pk2(av[i], av[i]);
                acc[i][0] = ffma2(a2, b.x, acc[i][0]);
                acc[i][1] = ffma2(a2, b.y, acc[i][1]);
            }
        }
        __syncthreads();
    }

#pragma unroll
    for (int i = 0; i < 8; i++) {
        float o0, o1, o2, o3;
        upk2(acc[i][0], o0, o1);
        upk2(acc[i][1], o2, o3);
        *(float4 *)(C + (mb + ty * 8 + i) * NH + nb + tx * 4) =
            make_float4(o0, o1, o2, o3);
    }
}

// ---------------------------------------------------------------------------
// Attention kernel: processes PAIRS of q-rows so each K-row load (phase 1)
// and each V-row load (phase 3) is amortized over 2 queries -> halves L1
// wavefront traffic, the measured bottleneck. 256 threads, 4 CTAs/SM.
// Phase 1: warp w computes keys {w, w+8, ...} < vlen; lanes split H (8 each).
// ---------------------------------------------------------------------------
#define ATT_GRID 592
#define NBLK (NB * NQ / 2)   // 1024 row-pairs

__global__ __launch_bounds__(256, 4)
void attn_kernel(const float *__restrict__ values, const float *__restrict__ Wv,
                 const int *__restrict__ vlens, float *__restrict__ out)
{
    __shared__ float  s_sc[2][NK];
    __shared__ float  s_red[2][8];
    __shared__ float4 s_acc[2][3][64];

    const int tid  = threadIdx.x;
    const int lane = tid & 31;
    const int warp = tid >> 5;

    const float4 wv0 = *(const float4 *)(Wv + lane * 8);
    const float4 wv1 = *(const float4 *)(Wv + lane * 8 + 4);

    for (int blk = blockIdx.x; blk < NBLK; blk += ATT_GRID) {
        const int row0 = blk * 2;
        const int b = row0 >> 7;
        const int vlen = vlens[b];

        const float *qr0 = g_qp + row0 * NH + lane * 8;
        const float4 qa0 = *(const float4 *)qr0;
        const float4 qa1 = *(const float4 *)(qr0 + 4);
        const float4 qb0 = *(const float4 *)(qr0 + NH);
        const float4 qb1 = *(const float4 *)(qr0 + NH + 4);
        const float *kbase = g_kp + b * NK * NH + lane * 8;

        // ---- Phase 1: scores for both rows, keys < vlen only ----
        for (int k = warp; k < vlen; k += 8) {
            const float *kr = kbase + k * NH;
            const float4 a0 = *(const float4 *)kr;
            const float4 a1 = *(const float4 *)(kr + 4);

            float t;
            t = tanh_fast(qa0.x + a0.x); float p0 = wv0.x * t;
            t = tanh_fast(qb0.x + a0.x); float p1 = wv0.x * t;
            t = tanh_fast(qa0.y + a0.y); p0 = fmaf(wv0.y, t, p0);
            t = tanh_fast(qb0.y + a0.y); p1 = fmaf(wv0.y, t, p1);
            t = tanh_fast(qa0.z + a0.z); p0 = fmaf(wv0.z, t, p0);
            t = tanh_fast(qb0.z + a0.z); p1 = fmaf(wv0.z, t, p1);
            t = tanh_fast(qa0.w + a0.w); p0 = fmaf(wv0.w, t, p0);
            t = tanh_fast(qb0.w + a0.w); p1 = fmaf(wv0.w, t, p1);
            t = tanh_fast(qa1.x + a1.x); p0 = fmaf(wv1.x, t, p0);
            t = tanh_fast(qb1.x + a1.x); p1 = fmaf(wv1.x, t, p1);
            t = tanh_fast(qa1.y + a1.y); p0 = fmaf(wv1.y, t, p0);
            t = tanh_fast(qb1.y + a1.y); p1 = fmaf(wv1.y, t, p1);
            t = tanh_fast(qa1.z + a1.z); p0 = fmaf(wv1.z, t, p0);
            t = tanh_fast(qb1.z + a1.z); p1 = fmaf(wv1.z, t, p1);
            t = tanh_fast(qa1.w + a1.w); p0 = fmaf(wv1.w, t, p0);
            t = tanh_fast(qb1.w + a1.w); p1 = fmaf(wv1.w, t, p1);

#pragma unroll
            for (int o = 16; o > 0; o >>= 1) {
                p0 += __shfl_xor_sync(0xffffffffu, p0, o);
                p1 += __shfl_xor_sync(0xffffffffu, p1, o);
            }
            if (lane == 0) { s_sc[0][k] = p0; s_sc[1][k] = p1; }
        }
        __syncthreads();

        // ---- Phase 2: masked softmax for both rows ----
        const float sa0 = (tid < vlen) ? s_sc[0][tid] : -1e6f;
        const float sa1 = (tid + 256 < vlen) ? s_sc[0][tid + 256] : -1e6f;
        const float sb0 = (tid < vlen) ? s_sc[1][tid] : -1e6f;
        const float sb1 = (tid + 256 < vlen) ? s_sc[1][tid + 256] : -1e6f;

        float m0 = fmaxf(sa0, sa1);
        float m1 = fmaxf(sb0, sb1);
#pragma unroll
        for (int o = 16; o > 0; o >>= 1) {
            m0 = fmaxf(m0, __shfl_xor_sync(0xffffffffu, m0, o));
            m1 = fmaxf(m1, __shfl_xor_sync(0xffffffffu, m1, o));
        }
        if (lane == 0) { s_red[0][warp] = m0; s_red[1][warp] = m1; }
        __syncthreads();
        float bm0 = s_red[0][0], bm1 = s_red[1][0];
#pragma unroll
        for (int j = 1; j < 8; j++) {
            bm0 = fmaxf(bm0, s_red[0][j]);
            bm1 = fmaxf(bm1, s_red[1][j]);
        }

        const float ea0 = __expf(sa0 - bm0);
        const float ea1 = __expf(sa1 - bm0);
        const float eb0 = __expf(sb0 - bm1);
        const float eb1 = __expf(sb1 - bm1);
        __syncthreads();                 // s_red(max) consumed by all
        s_sc[0][tid] = ea0;  s_sc[0][tid + 256] = ea1;
        s_sc[1][tid] = eb0;  s_sc[1][tid + 256] = eb1;

        float ps0 = ea0 + ea1, ps1 = eb0 + eb1;
#pragma unroll
        for (int o = 16; o > 0; o >>= 1) {
            ps0 += __shfl_xor_sync(0xffffffffu, ps0, o);
            ps1 += __shfl_xor_sync(0xffffffffu, ps1, o);
        }
        if (lane == 0) { s_red[0][warp] = ps0; s_red[1][warp] = ps1; }
        __syncthreads();
        float tot0 = 0.f, tot1 = 0.f;
#pragma unroll
        for (int j = 0; j < 8; j++) { tot0 += s_red[0][j]; tot1 += s_red[1][j]; }
        const float inv0 = 1.0f / tot0;
        const float inv1 = 1.0f / tot1;

        // ---- Phase 3: out = attn @ V, V row shared by both q-rows ----
        const int vq  = tid & 63;        // column group (4 floats)
        const int kof = tid >> 6;        // key offset group 0..3
        const float *vb = values + b * NK * NV + vq * 4;
        float4 ac0 = make_float4(0.f, 0.f, 0.f, 0.f);
        float4 ac1 = make_float4(0.f, 0.f, 0.f, 0.f);
#pragma unroll 4
        for (int k = kof; k < vlen; k += 4) {
            const float w0 = s_sc[0][k];
            const float w1 = s_sc[1][k];
            const float4 v = *(const float4 *)(vb + k * NV);
            ac0.x = fmaf(w0, v.x, ac0.x);  ac1.x = fmaf(w1, v.x, ac1.x);
            ac0.y = fmaf(w0, v.y, ac0.y);  ac1.y = fmaf(w1, v.y, ac1.y);
            ac0.z = fmaf(w0, v.z, ac0.z);  ac1.z = fmaf(w1, v.z, ac1.z);
            ac0.w = fmaf(w0, v.w, ac0.w);  ac1.w = fmaf(w1, v.w, ac1.w);
        }
        if (kof > 0) {
            s_acc[0][kof - 1][vq] = ac0;
            s_acc[1][kof - 1][vq] = ac1;
        }
        __syncthreads();
        if (kof == 0) {
            float4 x;
#pragma unroll
            for (int j = 0; j < 3; j++) {
                x = s_acc[0][j][vq];
                ac0.x += x.x; ac0.y += x.y; ac0.z += x.z; ac0.w += x.w;
                x = s_acc[1][j][vq];
                ac1.x += x.x; ac1.y += x.y; ac1.z += x.z; ac1.w += x.w;
            }
            ac0.x *= inv0; ac0.y *= inv0; ac0.z *= inv0; ac0.w *= inv0;
            ac1.x *= inv1; ac1.y *= inv1; ac1.z *= inv1; ac1.w *= inv1;
            *(float4 *)(out + row0 * NV + vq * 4) = ac0;
            *(float4 *)(out + (row0 + 1) * NV + vq * 4) = ac1;
        }
        __syncthreads();
    }
}

// ---------------------------------------------------------------------------
extern "C" void kernel_launch(void *const *d_in, const int *in_sizes, int n_in,
                              void *d_out, int out_size)
{
    const float *queries = (const float *)d_in[0];
    const float *keys    = (const float *)d_in[1];
    const float *values  = (const float *)d_in[2];
    const float *Wq      = (const float *)d_in[3];
    const float *Wk      = (const float *)d_in[4];
    const float *Wv      = (const float *)d_in[5];
    const int   *vlens   = (const int *)d_in[6];
    float *out = (float *)d_out;

    float *qp_ptr = nullptr, *kp_ptr = nullptr;
    cudaGetSymbolAddress((void **)&qp_ptr, g_qp);
    cudaGetSymbolAddress((void **)&kp_ptr, g_kp);

    proj_gemm_kernel<<<dim3(QTILES + KTILES, NH / 64), 128>>>(
        queries, Wq, keys, Wk, vlens, qp_ptr, kp_ptr);
    attn_kernel<<<ATT_GRID, 256>>>(values, Wv, vlens, out);
}

// round 17
// speedup vs baseline: 1.1664x; 1.0022x over previous
#include <cuda_runtime.h>

// Problem dims
#define NB   16      // batch
#define NQ   128     // queries
#define NK   512     // keys
#define NH   256     // hidden
#define NV   256     // value dim

// Scratch for projected q/k (no cudaMalloc allowed)
__device__ float g_qp[NB * NQ * NH];   // 2 MB
__device__ float g_kp[NB * NK * NH];   // 8 MB

// ---------------------------------------------------------------------------
// helpers
// ---------------------------------------------------------------------------
__device__ __forceinline__ float tanh_fast(float x) {
    float y;
    asm("tanh.approx.f32 %0, %1;" : "=f"(y) : "f"(x));
    return y;
}
__device__ __forceinline__ unsigned long long pk2(float lo, float hi) {
    unsigned long long r;
    asm("mov.b64 %0, {%1, %2};" : "=l"(r) : "f"(lo), "f"(hi));
    return r;
}
__device__ __forceinline__ void upk2(unsigned long long v, float &lo, float &hi) {
    asm("mov.b64 {%0, %1}, %2;" : "=f"(lo), "=f"(hi) : "l"(v));
}
__device__ __forceinline__ unsigned long long ffma2(unsigned long long a,
                                                    unsigned long long b,
                                                    unsigned long long c) {
    unsigned long long d;
    asm("fma.rn.f32x2 %0, %1, %2, %3;" : "=l"(d) : "l"(a), "l"(b), "l"(c));
    return d;
}

// ---------------------------------------------------------------------------
// Projection GEMM:  C[m, n] = sum_d A[m, d] * W[n, d]   (both K-major, NT)
// BM=64, BN=64, BK=32, 128 threads, 8x4 microtile, f32x2 FFMA2 accumulators.
// block.x tiles 0..31 -> queries/Wq -> g_qp; 32..159 -> keys/Wk -> g_kp.
// Key tiles entirely beyond valid_len[batch] exit immediately (finer 64-row
// granularity than before).
// ---------------------------------------------------------------------------
#define QTILES 32    // 2048 / 64
#define KTILES 128   // 8192 / 64

__global__ __launch_bounds__(128)
void proj_gemm_kernel(const float *__restrict__ Aq, const float *__restrict__ Wq,
                      const float *__restrict__ Ak, const float *__restrict__ Wk,
                      const int *__restrict__ vlens,
                      float *__restrict__ Cq, float *__restrict__ Ck)
{
    __shared__ float As[32][68];    // [k][m], padded: conflict-free LDS
    __shared__ float Bs[32][64];    // [k][n]

    const int tid = threadIdx.x;
    const int bx  = blockIdx.x;

    const float *A, *W;
    float *C;
    int mb;
    if (bx < QTILES) { A = Aq; W = Wq; C = Cq; mb = bx * 64; }
    else {
        A = Ak; W = Wk; C = Ck; mb = (bx - QTILES) * 64;
        const int batch = mb >> 9;          // / NK
        const int local = mb & (NK - 1);
        if (local >= vlens[batch]) return;  // output never read
    }
    const int nb = blockIdx.y * 64;

    const int tx = tid & 15;   // 0..15 -> cols tx*4
    const int ty = tid >> 4;   // 0..7  -> rows ty*8

    const int arow  = tid >> 1;        // 0..63
    const int ahalf = tid & 1;         // 0..1 (16 k-floats each)

    unsigned long long acc[8][2];
#pragma unroll
    for (int i = 0; i < 8; i++) { acc[i][0] = 0ULL; acc[i][1] = 0ULL; }

    for (int kb = 0; kb < NH; kb += 32) {
        // A tile: 64 rows x 32 k. Thread: row=tid>>1, 16 k-floats (4 float4)
#pragma unroll
        for (int j = 0; j < 4; j++) {
            const int k0 = ahalf * 16 + j * 4;
            float4 v = *(const float4 *)(A + (mb + arow) * NH + kb + k0);
            As[k0 + 0][arow] = v.x;
            As[k0 + 1][arow] = v.y;
            As[k0 + 2][arow] = v.z;
            As[k0 + 3][arow] = v.w;
        }
        // W tile: 64 n-rows x 32 k = 512 float4, 4 per thread
#pragma unroll
        for (int j = 0; j < 4; j++) {
            const int idx = tid + 128 * j;
            const int n = idx & 63, kq = idx >> 6;
            float4 v = *(const float4 *)(W + (nb + n) * NH + kb + kq * 4);
            Bs[kq * 4 + 0][n] = v.x;
            Bs[kq * 4 + 1][n] = v.y;
            Bs[kq * 4 + 2][n] = v.z;
            Bs[kq * 4 + 3][n] = v.w;
        }
        __syncthreads();

#pragma unroll 8
        for (int kk = 0; kk < 32; kk++) {
            float4 aa0 = *(const float4 *)&As[kk][ty * 8];
            float4 aa1 = *(const float4 *)&As[kk][ty * 8 + 4];
            ulonglong2 b = *(const ulonglong2 *)&Bs[kk][tx * 4];
            float av[8] = {aa0.x, aa0.y, aa0.z, aa0.w, aa1.x, aa1.y, aa1.z, aa1.w};
#pragma unroll
            for (int i = 0; i < 8; i++) {
                unsigned long long a2 = pk2(av[i], av[i]);
                acc[i][0] = ffma2(a2, b.x, acc[i][0]);
                acc[i][1] = ffma2(a2, b.y, acc[i][1]);
            }
        }
        __syncthreads();
    }

#pragma unroll
    for (int i = 0; i < 8; i++) {
        float o0, o1, o2, o3;
        upk2(acc[i][0], o0, o1);
        upk2(acc[i][1], o2, o3);
        *(float4 *)(C + (mb + ty * 8 + i) * NH + nb + tx * 4) =
            make_float4(o0, o1, o2, o3);
    }
}

// ---------------------------------------------------------------------------
// Attention kernel: processes PAIRS of q-rows so each K-row load (phase 1)
// and each V-row load (phase 3) is amortized over 2 queries -> halves L1
// wavefront traffic, the measured bottleneck. 256 threads, 4 CTAs/SM.
// Phase 1: warp w computes keys {w, w+8, ...} < vlen; lanes split H (8 each).
// ---------------------------------------------------------------------------
#define ATT_GRID 592
#define NBLK (NB * NQ / 2)   // 1024 row-pairs

__global__ __launch_bounds__(256, 4)
void attn_kernel(const float *__restrict__ values, const float *__restrict__ Wv,
                 const int *__restrict__ vlens, float *__restrict__ out)
{
    __shared__ float  s_sc[2][NK];
    __shared__ float  s_red[2][8];
    __shared__ float4 s_acc[2][3][64];

    const int tid  = threadIdx.x;
    const int lane = tid & 31;
    const int warp = tid >> 5;

    const float4 wv0 = *(const float4 *)(Wv + lane * 8);
    const float4 wv1 = *(const float4 *)(Wv + lane * 8 + 4);

    for (int blk = blockIdx.x; blk < NBLK; blk += ATT_GRID) {
        const int row0 = blk * 2;
        const int b = row0 >> 7;
        const int vlen = vlens[b];

        const float *qr0 = g_qp + row0 * NH + lane * 8;
        const float4 qa0 = *(const float4 *)qr0;
        const float4 qa1 = *(const float4 *)(qr0 + 4);
        const float4 qb0 = *(const float4 *)(qr0 + NH);
        const float4 qb1 = *(const float4 *)(qr0 + NH + 4);
        const float *kbase = g_kp + b * NK * NH + lane * 8;

        // ---- Phase 1: scores for both rows, keys < vlen only ----
        for (int k = warp; k < vlen; k += 8) {
            const float *kr = kbase + k * NH;
            const float4 a0 = *(const float4 *)kr;
            const float4 a1 = *(const float4 *)(kr + 4);

            float t;
            t = tanh_fast(qa0.x + a0.x); float p0 = wv0.x * t;
            t = tanh_fast(qb0.x + a0.x); float p1 = wv0.x * t;
            t = tanh_fast(qa0.y + a0.y); p0 = fmaf(wv0.y, t, p0);
            t = tanh_fast(qb0.y + a0.y); p1 = fmaf(wv0.y, t, p1);
            t = tanh_fast(qa0.z + a0.z); p0 = fmaf(wv0.z, t, p0);
            t = tanh_fast(qb0.z + a0.z); p1 = fmaf(wv0.z, t, p1);
            t = tanh_fast(qa0.w + a0.w); p0 = fmaf(wv0.w, t, p0);
            t = tanh_fast(qb0.w + a0.w); p1 = fmaf(wv0.w, t, p1);
            t = tanh_fast(qa1.x + a1.x); p0 = fmaf(wv1.x, t, p0);
            t = tanh_fast(qb1.x + a1.x); p1 = fmaf(wv1.x, t, p1);
            t = tanh_fast(qa1.y + a1.y); p0 = fmaf(wv1.y, t, p0);
            t = tanh_fast(qb1.y + a1.y); p1 = fmaf(wv1.y, t, p1);
            t = tanh_fast(qa1.z + a1.z); p0 = fmaf(wv1.z, t, p0);
            t = tanh_fast(qb1.z + a1.z); p1 = fmaf(wv1.z, t, p1);
            t = tanh_fast(qa1.w + a1.w); p0 = fmaf(wv1.w, t, p0);
            t = tanh_fast(qb1.w + a1.w); p1 = fmaf(wv1.w, t, p1);

#pragma unroll
            for (int o = 16; o > 0; o >>= 1) {
                p0 += __shfl_xor_sync(0xffffffffu, p0, o);
                p1 += __shfl_xor_sync(0xffffffffu, p1, o);
            }
            if (lane == 0) { s_sc[0][k] = p0; s_sc[1][k] = p1; }
        }
        __syncthreads();

        // ---- Phase 2: masked softmax for both rows ----
        const float sa0 = (tid < vlen) ? s_sc[0][tid] : -1e6f;
        const float sa1 = (tid + 256 < vlen) ? s_sc[0][tid + 256] : -1e6f;
        const float sb0 = (tid < vlen) ? s_sc[1][tid] : -1e6f;
        const float sb1 = (tid + 256 < vlen) ? s_sc[1][tid + 256] : -1e6f;

        float m0 = fmaxf(sa0, sa1);
        float m1 = fmaxf(sb0, sb1);
#pragma unroll
        for (int o = 16; o > 0; o >>= 1) {
            m0 = fmaxf(m0, __shfl_xor_sync(0xffffffffu, m0, o));
            m1 = fmaxf(m1, __shfl_xor_sync(0xffffffffu, m1, o));
        }
        if (lane == 0) { s_red[0][warp] = m0; s_red[1][warp] = m1; }
        __syncthreads();
        float bm0 = s_red[0][0], bm1 = s_red[1][0];
#pragma unroll
        for (int j = 1; j < 8; j++) {
            bm0 = fmaxf(bm0, s_red[0][j]);
            bm1 = fmaxf(bm1, s_red[1][j]);
        }

        const float ea0 = __expf(sa0 - bm0);
        const float ea1 = __expf(sa1 - bm0);
        const float eb0 = __expf(sb0 - bm1);
        const float eb1 = __expf(sb1 - bm1);
        __syncthreads();                 // s_red(max) consumed by all
        s_sc[0][tid] = ea0;  s_sc[0][tid + 256] = ea1;
        s_sc[1][tid] = eb0;  s_sc[1][tid + 256] = eb1;

        float ps0 = ea0 + ea1, ps1 = eb0 + eb1;
#pragma unroll
        for (int o = 16; o > 0; o >>= 1) {
            ps0 += __shfl_xor_sync(0xffffffffu, ps0, o);
            ps1 += __shfl_xor_sync(0xffffffffu, ps1, o);
        }
        if (lane == 0) { s_red[0][warp] = ps0; s_red[1][warp] = ps1; }
        __syncthreads();
        float tot0 = 0.f, tot1 = 0.f;
#pragma unroll
        for (int j = 0; j < 8; j++) { tot0 += s_red[0][j]; tot1 += s_red[1][j]; }
        const float inv0 = 1.0f / tot0;
        const float inv1 = 1.0f / tot1;

        // ---- Phase 3: out = attn @ V, V row shared by both q-rows ----
        const int vq  = tid & 63;        // column group (4 floats)
        const int kof = tid >> 6;        // key offset group 0..3
        const float *vb = values + b * NK * NV + vq * 4;
        float4 ac0 = make_float4(0.f, 0.f, 0.f, 0.f);
        float4 ac1 = make_float4(0.f, 0.f, 0.f, 0.f);
#pragma unroll 4
        for (int k = kof; k < vlen; k += 4) {
            const float w0 = s_sc[0][k];
            const float w1 = s_sc[1][k];
            const float4 v = *(const float4 *)(vb + k * NV);
            ac0.x = fmaf(w0, v.x, ac0.x);  ac1.x = fmaf(w1, v.x, ac1.x);
            ac0.y = fmaf(w0, v.y, ac0.y);  ac1.y = fmaf(w1, v.y, ac1.y);
            ac0.z = fmaf(w0, v.z, ac0.z);  ac1.z = fmaf(w1, v.z, ac1.z);
            ac0.w = fmaf(w0, v.w, ac0.w);  ac1.w = fmaf(w1, v.w, ac1.w);
        }
        if (kof > 0) {
            s_acc[0][kof - 1][vq] = ac0;
            s_acc[1][kof - 1][vq] = ac1;
        }
        __syncthreads();
        if (kof == 0) {
            float4 x;
#pragma unroll
            for (int j = 0; j < 3; j++) {
                x = s_acc[0][j][vq];
                ac0.x += x.x; ac0.y += x.y; ac0.z += x.z; ac0.w += x.w;
                x = s_acc[1][j][vq];
                ac1.x += x.x; ac1.y += x.y; ac1.z += x.z; ac1.w += x.w;
            }
            ac0.x *= inv0; ac0.y *= inv0; ac0.z *= inv0; ac0.w *= inv0;
            ac1.x *= inv1; ac1.y *= inv1; ac1.z *= inv1; ac1.w *= inv1;
            *(float4 *)(out + row0 * NV + vq * 4) = ac0;
            *(float4 *)(out + (row0 + 1) * NV + vq * 4) = ac1;
        }
        __syncthreads();
    }
}

// ---------------------------------------------------------------------------
extern "C" void kernel_launch(void *const *d_in, const int *in_sizes, int n_in,
                              void *d_out, int out_size)
{
    const float *queries = (const float *)d_in[0];
    const float *keys    = (const float *)d_in[1];
    const float *values  = (const float *)d_in[2];
    const float *Wq      = (const float *)d_in[3];
    const float *Wk      = (const float *)d_in[4];
    const float *Wv      = (const float *)d_in[5];
    const int   *vlens   = (const int *)d_in[6];
    float *out = (float *)d_out;

    float *qp_ptr = nullptr, *kp_ptr = nullptr;
    cudaGetSymbolAddress((void **)&qp_ptr, g_qp);
    cudaGetSymbolAddress((void **)&kp_ptr, g_kp);

    proj_gemm_kernel<<<dim3(QTILES + KTILES, NH / 64), 128>>>(
        queries, Wq, keys, Wk, vlens, qp_ptr, kp_ptr);
    attn_kernel<<<ATT_GRID, 256>>>(values, Wv, vlens, out);
}